// round 1
// baseline (speedup 1.0000x reference)
#include <cuda_runtime.h>
#include <math.h>

// ---------------- problem constants ----------------
#define CC    192          // dim
#define TT    16
#define HH    64
#define WW    64
#define HS    16           // H/4
#define WS    16           // W/4
#define LL    4096         // T*HS*WS
#define DI    384          // d_inner
#define DS    16           // d_state
#define DTR   12           // dt_rank
#define XDW   44           // dt_rank + 2*d_state
#define NCH   64           // scan chunks
#define CLEN  64           // chunk length  (NCH*CLEN == LL)

// ---------------- scratch (device globals; no allocs) ----------------
__device__ float g_tokens[LL*CC];
__device__ float g_yln   [LL*CC];
__device__ float g_xz    [LL*2*DI];
__device__ float g_xs    [LL*DI];
__device__ float g_xdbl  [LL*XDW];
__device__ float g_dt    [LL*DI];
__device__ float g_A     [DI*DS];
__device__ float g_hc    [NCH*DI*DS];
__device__ float g_hin   [NCH*DI*DS];
__device__ float g_dts   [NCH*DI];
__device__ float g_y     [LL*DI];
__device__ float g_om    [LL*CC];
__device__ float g_ln2   [LL*CC];
__device__ float g_w     [CC];

// ---------------- helpers ----------------
__device__ __forceinline__ float silu_f(float v) {
    return v / (1.f + __expf(-v));
}
__device__ __forceinline__ float sigmoid_f(float v) {
    return 1.f / (1.f + __expf(-v));
}

// ============ K1: 4x4 avg pool -> tokens (L, C) ============
__global__ void k_pool(const float* __restrict__ x) {
    int idx = blockIdx.x * blockDim.x + threadIdx.x;       // 192*4096
    int c = idx >> 12;            // / 4096
    int l = idx & 4095;
    int t  = l >> 8;
    int hs = (l >> 4) & 15;
    int ws = l & 15;
    // base of the 4x4 block: x[c][t][4hs][4ws]
    long base = (((long)c * TT + t) * HH + hs * 4) * WW + ws * 4;
    float s = 0.f;
    #pragma unroll
    for (int r = 0; r < 4; r++) {
        float4 v = *reinterpret_cast<const float4*>(x + base + (long)r * WW);
        s += v.x + v.y + v.z + v.w;
    }
    g_tokens[l * CC + c] = s * (1.f / 16.f);
}

// ============ K2: LayerNorm over C (optionally with residual add) ============
__global__ void k_ln(const float* __restrict__ in, const float* __restrict__ add,
                     const float* __restrict__ g, const float* __restrict__ b,
                     float* __restrict__ out) {
    int l = blockIdx.x;
    int c = threadIdx.x;                       // 192 threads = 6 warps
    float v = in[l * CC + c];
    if (add) v += add[l * CC + c];
    float s = v, q = v * v;
    __shared__ float sh_s[6], sh_q[6];
    __shared__ float sh_mean, sh_rstd;
    int warp = c >> 5, lane = c & 31;
    #pragma unroll
    for (int o = 16; o > 0; o >>= 1) {
        s += __shfl_down_sync(0xffffffffu, s, o);
        q += __shfl_down_sync(0xffffffffu, q, o);
    }
    if (lane == 0) { sh_s[warp] = s; sh_q[warp] = q; }
    __syncthreads();
    if (c == 0) {
        float ts = 0.f, tq = 0.f;
        #pragma unroll
        for (int i = 0; i < 6; i++) { ts += sh_s[i]; tq += sh_q[i]; }
        float m = ts * (1.f / CC);
        float var = tq * (1.f / CC) - m * m;
        sh_mean = m;
        sh_rstd = rsqrtf(var + 1e-5f);
    }
    __syncthreads();
    out[l * CC + c] = (v - sh_mean) * sh_rstd * g[c] + b[c];
}

// ============ GEMM (TN):  C[m][n] = sum_k A[m*K+k] * B[n*K+k] ============
// BM=128, BN=64, BK=16, TM=8, TN=4, block (16,16)=256 threads
__global__ void gemm_tn(const float* __restrict__ A, const float* __restrict__ B,
                        float* __restrict__ C, int M, int N, int K) {
    const int BM = 128, BN = 64, BK = 16;
    __shared__ float As[BK][BM + 4];
    __shared__ float Bs[BK][BN + 4];
    int tx = threadIdx.x, ty = threadIdx.y;
    int tid = ty * 16 + tx;
    int m0 = blockIdx.y * BM, n0 = blockIdx.x * BN;
    float acc[8][4];
    #pragma unroll
    for (int i = 0; i < 8; i++)
        #pragma unroll
        for (int j = 0; j < 4; j++) acc[i][j] = 0.f;

    for (int k0 = 0; k0 < K; k0 += BK) {
        // load A tile (BM x BK), transposed into As[k][m]
        #pragma unroll
        for (int it = 0; it < (BM * BK) / 256; it++) {
            int i = tid + it * 256;
            int m = i >> 4, k = i & 15;
            float v = 0.f;
            if (m0 + m < M) v = A[(long)(m0 + m) * K + k0 + k];
            As[k][m] = v;
        }
        // load B tile (BN x BK)
        #pragma unroll
        for (int it = 0; it < (BN * BK) / 256; it++) {
            int i = tid + it * 256;
            int n = i >> 4, k = i & 15;
            float v = 0.f;
            if (n0 + n < N) v = B[(long)(n0 + n) * K + k0 + k];
            Bs[k][n] = v;
        }
        __syncthreads();
        #pragma unroll
        for (int kk = 0; kk < BK; kk++) {
            float4 a0 = *reinterpret_cast<const float4*>(&As[kk][ty * 8]);
            float4 a1 = *reinterpret_cast<const float4*>(&As[kk][ty * 8 + 4]);
            float4 b0 = *reinterpret_cast<const float4*>(&Bs[kk][tx * 4]);
            float a[8] = {a0.x, a0.y, a0.z, a0.w, a1.x, a1.y, a1.z, a1.w};
            float b[4] = {b0.x, b0.y, b0.z, b0.w};
            #pragma unroll
            for (int tm = 0; tm < 8; tm++)
                #pragma unroll
                for (int tn = 0; tn < 4; tn++)
                    acc[tm][tn] += a[tm] * b[tn];
        }
        __syncthreads();
    }
    #pragma unroll
    for (int tm = 0; tm < 8; tm++) {
        int m = m0 + ty * 8 + tm;
        if (m < M) {
            #pragma unroll
            for (int tn = 0; tn < 4; tn++) {
                int n = n0 + tx * 4 + tn;
                if (n < N) C[(long)m * N + n] = acc[tm][tn];
            }
        }
    }
}

// ============ K3: causal depthwise conv1d (k=4) + SiLU -> xs ============
__global__ void k_conv(const float* __restrict__ cw, const float* __restrict__ cb) {
    int idx = blockIdx.x * blockDim.x + threadIdx.x;       // LL*DI
    int l = idx / DI, d = idx % DI;
    float4 w = *reinterpret_cast<const float4*>(cw + d * 4);
    float acc = cb[d];
    if (l >= 3) acc += w.x * g_xz[(l - 3) * (2 * DI) + d];
    if (l >= 2) acc += w.y * g_xz[(l - 2) * (2 * DI) + d];
    if (l >= 1) acc += w.z * g_xz[(l - 1) * (2 * DI) + d];
    acc += w.w * g_xz[l * (2 * DI) + d];
    g_xs[idx] = silu_f(acc);
}

// ============ K4: dt = softplus(xdbl[:, :12] @ W_dt^T + b_dt) ============
__global__ void k_dt(const float* __restrict__ Wdt, const float* __restrict__ bdt) {
    int l = blockIdx.x;
    int d = threadIdx.x;                  // 384
    __shared__ float xd[DTR];
    if (d < DTR) xd[d] = g_xdbl[l * XDW + d];
    __syncthreads();
    float acc = bdt[d];
    #pragma unroll
    for (int r = 0; r < DTR; r++) acc += xd[r] * Wdt[d * DTR + r];
    float e = __expf(-fabsf(acc));
    g_dt[l * DI + d] = fmaxf(acc, 0.f) + log1pf(e);
}

// ============ K5: A = -exp(A_log) ============
__global__ void k_A(const float* __restrict__ Alog) {
    int i = blockIdx.x * blockDim.x + threadIdx.x;
    if (i < DI * DS) g_A[i] = -expf(Alog[i]);
}

// ============ scan phase 1: per-chunk local state + dt sum ============
__global__ void k_scan1() {
    int chunk = blockIdx.y;
    int d = blockIdx.x * 128 + threadIdx.x;                 // 3 x 128 = 384
    __shared__ float sB[CLEN][DS];
    for (int i = threadIdx.x; i < CLEN * DS; i += 128) {
        int r = i >> 4, s = i & 15;
        sB[r][s] = g_xdbl[(chunk * CLEN + r) * XDW + DTR + s];
    }
    __syncthreads();
    float Ad[DS], h[DS];
    #pragma unroll
    for (int s = 0; s < DS; s++) { Ad[s] = g_A[d * DS + s]; h[s] = 0.f; }
    float dsum = 0.f;
    for (int i = 0; i < CLEN; i++) {
        int l = chunk * CLEN + i;
        float dtv = g_dt[l * DI + d];
        float xv  = g_xs[l * DI + d];
        float dtx = dtv * xv;
        dsum += dtv;
        #pragma unroll
        for (int s = 0; s < DS; s++)
            h[s] = __expf(dtv * Ad[s]) * h[s] + dtx * sB[i][s];
    }
    int base = (chunk * DI + d) * DS;
    #pragma unroll
    for (int s = 0; s < DS; s++) g_hc[base + s] = h[s];
    g_dts[chunk * DI + d] = dsum;
}

// ============ scan phase 2: inter-chunk prefix ============
__global__ void k_scan2() {
    int idx = blockIdx.x * blockDim.x + threadIdx.x;        // DI*DS = 6144
    if (idx >= DI * DS) return;
    int d = idx >> 4;
    float a = g_A[idx];
    float h = 0.f;
    for (int c = 0; c < NCH; c++) {
        int off = (c * DI + d) * DS + (idx & 15);
        g_hin[off] = h;
        h = __expf(g_dts[c * DI + d] * a) * h + g_hc[off];
    }
}

// ============ scan phase 3: recompute with carry, emit gated y ============
__global__ void k_scan3(const float* __restrict__ Dp) {
    int chunk = blockIdx.y;
    int d = blockIdx.x * 128 + threadIdx.x;
    __shared__ float sB[CLEN][DS];
    __shared__ float sC[CLEN][DS];
    for (int i = threadIdx.x; i < CLEN * DS; i += 128) {
        int r = i >> 4, s = i & 15;
        sB[r][s] = g_xdbl[(chunk * CLEN + r) * XDW + DTR + s];
        sC[r][s] = g_xdbl[(chunk * CLEN + r) * XDW + DTR + DS + s];
    }
    __syncthreads();
    float Ad[DS], h[DS];
    int base = (chunk * DI + d) * DS;
    #pragma unroll
    for (int s = 0; s < DS; s++) { Ad[s] = g_A[d * DS + s]; h[s] = g_hin[base + s]; }
    float Dd = Dp[d];
    for (int i = 0; i < CLEN; i++) {
        int l = chunk * CLEN + i;
        float dtv = g_dt[l * DI + d];
        float xv  = g_xs[l * DI + d];
        float dtx = dtv * xv;
        float yt = 0.f;
        #pragma unroll
        for (int s = 0; s < DS; s++) {
            h[s] = __expf(dtv * Ad[s]) * h[s] + dtx * sB[i][s];
            yt += h[s] * sC[i][s];
        }
        yt += xv * Dd;
        float zv = g_xz[l * (2 * DI) + DI + d];
        g_y[l * DI + d] = yt * silu_f(zv);
    }
}

// ============ K6: pooled -> 16pt rDFT bins 1..7 -> sigmoid weight ============
__global__ void k_freq() {
    int c = blockIdx.x;                       // 192
    int tid = threadIdx.x;                    // 256 = spatial position
    __shared__ float spart[8][16];
    __shared__ float sp[16];
    __shared__ float smag[8];
    int warp = tid >> 5, lane = tid & 31;
    for (int t = 0; t < TT; t++) {
        float v = g_ln2[(t * 256 + tid) * CC + c];
        #pragma unroll
        for (int o = 16; o > 0; o >>= 1) v += __shfl_down_sync(0xffffffffu, v, o);
        if (lane == 0) spart[warp][t] = v;
    }
    __syncthreads();
    if (tid < 16) {
        float s = 0.f;
        #pragma unroll
        for (int w = 0; w < 8; w++) s += spart[w][tid];
        sp[tid] = s * (1.f / 256.f);          // mean over 16x16 spatial
    }
    __syncthreads();
    if (tid >= 1 && tid < 8) {
        float re = 0.f, im = 0.f;
        for (int t = 0; t < TT; t++) {
            float ang = -2.f * 3.14159265358979323846f * (float)(tid * t) / 16.f;
            re += sp[t] * cosf(ang);
            im += sp[t] * sinf(ang);
        }
        smag[tid] = sqrtf(re * re + im * im);
    }
    __syncthreads();
    if (tid == 0) {
        float m = 0.f;
        #pragma unroll
        for (int k = 1; k < 8; k++) m += smag[k];
        m *= (1.f / 7.f);
        g_w[c] = 1.f / (1.f + expf(-m));
    }
}

// ============ K7: trilinear x4 upsample * weight * sigmoid(x) ============
__global__ void k_final(const float* __restrict__ x, float* __restrict__ out) {
    int idx = blockIdx.x * blockDim.x + threadIdx.x;        // 192*16*64*64
    int c = idx >> 16;
    int rem = idx & 65535;
    int t = rem >> 12;
    int h = (rem >> 6) & 63;
    int w = rem & 63;
    float sh = h * 0.25f - 0.375f;
    float sw = w * 0.25f - 0.375f;
    int ih = (int)floorf(sh); float fh = sh - (float)ih;
    int iw = (int)floorf(sw); float fw = sw - (float)iw;
    int h0 = min(max(ih, 0), 15),  h1 = min(max(ih + 1, 0), 15);
    int w0 = min(max(iw, 0), 15),  w1 = min(max(iw + 1, 0), 15);
    int bt = t << 8;
    float p00 = g_ln2[(bt + (h0 << 4) + w0) * CC + c];
    float p01 = g_ln2[(bt + (h0 << 4) + w1) * CC + c];
    float p10 = g_ln2[(bt + (h1 << 4) + w0) * CC + c];
    float p11 = g_ln2[(bt + (h1 << 4) + w1) * CC + c];
    float v = (1.f - fh) * ((1.f - fw) * p00 + fw * p01)
            +        fh  * ((1.f - fw) * p10 + fw * p11);
    v *= g_w[c];
    out[idx] = v * sigmoid_f(x[idx]);
}

// ---------------- launch ----------------
static float* sym_addr(const void* sym) {
    void* p = nullptr;
    cudaGetSymbolAddress(&p, sym);
    return (float*)p;
}

extern "C" void kernel_launch(void* const* d_in, const int* in_sizes, int n_in,
                              void* d_out, int out_size) {
    const float* x     = (const float*)d_in[0];
    const float* ln1g  = (const float*)d_in[1];
    const float* ln1b  = (const float*)d_in[2];
    const float* ln2g  = (const float*)d_in[3];
    const float* ln2b  = (const float*)d_in[4];
    const float* Win   = (const float*)d_in[5];
    const float* convw = (const float*)d_in[6];
    const float* convb = (const float*)d_in[7];
    const float* Wxp   = (const float*)d_in[8];
    const float* Wdt   = (const float*)d_in[9];
    const float* bdt   = (const float*)d_in[10];
    const float* Alog  = (const float*)d_in[11];
    const float* Dp    = (const float*)d_in[12];
    const float* Wout  = (const float*)d_in[13];
    float* out = (float*)d_out;

    float* p_tokens = sym_addr(g_tokens);
    float* p_yln    = sym_addr(g_yln);
    float* p_xz     = sym_addr(g_xz);
    float* p_xs     = sym_addr(g_xs);
    float* p_xdbl   = sym_addr(g_xdbl);
    float* p_y      = sym_addr(g_y);
    float* p_om     = sym_addr(g_om);
    float* p_ln2    = sym_addr(g_ln2);

    dim3 gblk(16, 16);

    // 1. pool -> tokens (L,C)
    k_pool<<<(CC * LL) / 256, 256>>>(x);
    // 2. LN1
    k_ln<<<LL, CC>>>(p_tokens, nullptr, ln1g, ln1b, p_yln);
    // 3. xz = yln @ W_in^T   (4096 x 768, K=192)
    gemm_tn<<<dim3(768 / 64, LL / 128), gblk>>>(p_yln, Win, p_xz, LL, 2 * DI, CC);
    // 4. depthwise causal conv + silu -> xs
    k_conv<<<(LL * DI) / 256, 256>>>(convw, convb);
    // 5. x_dbl = xs @ W_xp^T  (4096 x 44, K=384)
    gemm_tn<<<dim3(1, LL / 128), gblk>>>(p_xs, Wxp, p_xdbl, LL, XDW, DI);
    // 6. dt
    k_dt<<<LL, DI>>>(Wdt, bdt);
    // 7. A = -exp(A_log)
    k_A<<<(DI * DS + 255) / 256, 256>>>(Alog);
    // 8-10. chunked selective scan
    k_scan1<<<dim3(3, NCH), 128>>>();
    k_scan2<<<(DI * DS + 255) / 256, 256>>>();
    k_scan3<<<dim3(3, NCH), 128>>>(Dp);
    // 11. out_m = y @ W_out^T (4096 x 192, K=384)
    gemm_tn<<<dim3(192 / 64, LL / 128), gblk>>>(p_y, Wout, p_om, LL, CC, DI);
    // 12. LN2(tokens + out_m)
    k_ln<<<LL, CC>>>(p_tokens, p_om, ln2g, ln2b, p_ln2);
    // 13. frequency gate
    k_freq<<<CC, 256>>>();
    // 14. upsample * sigmoid(x)
    k_final<<<(CC * TT * HH * WW) / 256, 256>>>(x, out);
}

// round 2
// speedup vs baseline: 1.3703x; 1.3703x over previous
#include <cuda_runtime.h>
#include <math.h>

// ---------------- problem constants ----------------
#define CC    192          // dim
#define TT    16
#define HH    64
#define WW    64
#define LL    4096         // T * 16 * 16
#define DI    384          // d_inner
#define DS    16           // d_state
#define DTR   12           // dt_rank
#define XDW   44           // dt_rank + 2*d_state
#define NCH   64           // scan chunks
#define CLEN  64           // chunk length

// ---------------- scratch (device globals; no allocs) ----------------
__device__ float g_tokens[LL*CC];     // pooled tokens (L, C)
__device__ float g_yln   [LL*CC];     // LN1 output (L, C)
__device__ float g_xz    [LL*2*DI];
__device__ float g_xs    [LL*DI];
__device__ float g_xdbl  [LL*XDW];
__device__ float g_dt    [LL*DI];
__device__ float g_A     [DI*DS];
__device__ float g_hc    [NCH*DI*DS];
__device__ float g_hin   [NCH*DI*DS];
__device__ float g_dts   [NCH*DI];
__device__ float g_y     [LL*DI];
__device__ float g_om    [LL*CC];
__device__ float g_ln2T  [CC*LL];     // LN2 output TRANSPOSED (C, L)
__device__ float g_w     [CC];

// ---------------- helpers ----------------
__device__ __forceinline__ float silu_f(float v)    { return v / (1.f + __expf(-v)); }
__device__ __forceinline__ float sigmoid_f(float v) { return 1.f / (1.f + __expf(-v)); }

// ============ K1: fused 4x4 avg pool + LN1 + layout (L,C) ============
// block = (hs = blockIdx.x, t = blockIdx.y), 256 threads.
// Produces g_tokens (raw pooled) and g_yln (LN1) for 16 tokens.
__global__ __launch_bounds__(256) void k_pool_ln1(
    const float* __restrict__ x,
    const float* __restrict__ g1, const float* __restrict__ b1)
{
    __shared__ float sp[CC * 17];                 // [c][ws], pad 17
    int hs = blockIdx.x, t = blockIdx.y;
    int tid = threadIdx.x;
    int cg = tid >> 4, ws = tid & 15;

    #pragma unroll
    for (int iter = 0; iter < 12; iter++) {
        int c = iter * 16 + cg;
        float acc = 0.f;
        #pragma unroll
        for (int r = 0; r < 4; r++) {
            long off = (((long)(c * TT + t)) * HH + (hs * 4 + r)) * WW + ws * 4;
            float4 v = *reinterpret_cast<const float4*>(x + off);
            acc += v.x + v.y + v.z + v.w;
        }
        sp[c * 17 + ws] = acc * (1.f / 16.f);
    }
    __syncthreads();

    int w = tid >> 5, lane = tid & 31;
    #pragma unroll
    for (int j = 0; j < 2; j++) {
        int tok = w * 2 + j;
        int l = t * 256 + hs * 16 + tok;
        float v[6];
        float s = 0.f, q = 0.f;
        #pragma unroll
        for (int k = 0; k < 6; k++) {
            v[k] = sp[(lane + 32 * k) * 17 + tok];
            s += v[k];
            q += v[k] * v[k];
        }
        #pragma unroll
        for (int o = 16; o > 0; o >>= 1) {
            s += __shfl_xor_sync(0xffffffffu, s, o);
            q += __shfl_xor_sync(0xffffffffu, q, o);
        }
        float m = s * (1.f / CC);
        float var = q * (1.f / CC) - m * m;
        float rstd = rsqrtf(var + 1e-5f);
        #pragma unroll
        for (int k = 0; k < 6; k++) {
            int c = lane + 32 * k;
            g_tokens[l * CC + c] = v[k];
            g_yln[l * CC + c] = (v[k] - m) * rstd * g1[c] + b1[c];
        }
    }
}

// ============ templated TN GEMM: C[m][n] = sum_k A[m*K+k]*B[n*K+k] ============
template<int BM, int BN, int BK, int TM, int TN, bool GUARD_N>
__global__ __launch_bounds__((BM/TM)*(BN/TN)) void gemm_tn_t(
    const float* __restrict__ A, const float* __restrict__ B,
    float* __restrict__ C, int M, int N, int K)
{
    constexpr int NT = (BM / TM) * (BN / TN);
    __shared__ float As[BK * (BM + 4)];
    __shared__ float Bs[BK * (BN + 4)];
    int tx = threadIdx.x, ty = threadIdx.y;
    int tid = ty * (BN / TN) + tx;
    int m0 = blockIdx.y * BM, n0 = blockIdx.x * BN;

    float acc[TM][TN];
    #pragma unroll
    for (int i = 0; i < TM; i++)
        #pragma unroll
        for (int j = 0; j < TN; j++) acc[i][j] = 0.f;

    for (int k0 = 0; k0 < K; k0 += BK) {
        #pragma unroll
        for (int it = 0; it < (BM * BK) / NT; it++) {
            int i = tid + it * NT;
            int m = i / BK, k = i % BK;
            As[k * (BM + 4) + m] = A[(long)(m0 + m) * K + k0 + k];
        }
        #pragma unroll
        for (int it = 0; it < (BN * BK) / NT; it++) {
            int i = tid + it * NT;
            int n = i / BK, k = i % BK;
            float v = 0.f;
            if (!GUARD_N || (n0 + n) < N) v = B[(long)(n0 + n) * K + k0 + k];
            Bs[k * (BN + 4) + n] = v;
        }
        __syncthreads();
        #pragma unroll
        for (int kk = 0; kk < BK; kk++) {
            float a[TM], b[TN];
            #pragma unroll
            for (int i = 0; i < TM; i += 4) {
                float4 tv = *reinterpret_cast<const float4*>(&As[kk * (BM + 4) + ty * TM + i]);
                a[i] = tv.x; a[i+1] = tv.y; a[i+2] = tv.z; a[i+3] = tv.w;
            }
            if constexpr (TN % 4 == 0) {
                #pragma unroll
                for (int j = 0; j < TN; j += 4) {
                    float4 tv = *reinterpret_cast<const float4*>(&Bs[kk * (BN + 4) + tx * TN + j]);
                    b[j] = tv.x; b[j+1] = tv.y; b[j+2] = tv.z; b[j+3] = tv.w;
                }
            } else {
                #pragma unroll
                for (int j = 0; j < TN; j++) b[j] = Bs[kk * (BN + 4) + tx * TN + j];
            }
            #pragma unroll
            for (int i = 0; i < TM; i++)
                #pragma unroll
                for (int j = 0; j < TN; j++)
                    acc[i][j] += a[i] * b[j];
        }
        __syncthreads();
    }

    #pragma unroll
    for (int i = 0; i < TM; i++) {
        int m = m0 + ty * TM + i;
        if constexpr (TN % 4 == 0 && !GUARD_N) {
            #pragma unroll
            for (int j = 0; j < TN; j += 4) {
                float4 tv = make_float4(acc[i][j], acc[i][j+1], acc[i][j+2], acc[i][j+3]);
                *reinterpret_cast<float4*>(&C[(long)m * N + n0 + tx * TN + j]) = tv;
            }
        } else {
            #pragma unroll
            for (int j = 0; j < TN; j++) {
                int n = n0 + tx * TN + j;
                if (!GUARD_N || n < N) C[(long)m * N + n] = acc[i][j];
            }
        }
    }
}

// ============ K3: causal depthwise conv1d (k=4) + SiLU, float4 over channels ============
__global__ __launch_bounds__(256) void k_conv(const float* __restrict__ cw, const float* __restrict__ cb) {
    int idx4 = blockIdx.x * blockDim.x + threadIdx.x;     // LL * DI/4
    int l = idx4 / (DI / 4), dq = idx4 % (DI / 4);
    int d = dq * 4;
    float4 wv[4];
    #pragma unroll
    for (int ch = 0; ch < 4; ch++)
        wv[ch] = *reinterpret_cast<const float4*>(cw + (d + ch) * 4);
    float4 bv = *reinterpret_cast<const float4*>(cb + d);
    float a0 = bv.x, a1 = bv.y, a2 = bv.z, a3 = bv.w;
    #pragma unroll
    for (int tap = 0; tap < 4; tap++) {
        int li = l - (3 - tap);
        if (li >= 0) {
            float4 v = *reinterpret_cast<const float4*>(&g_xz[li * (2 * DI) + d]);
            float w0 = (&wv[0].x)[tap], w1 = (&wv[1].x)[tap],
                  w2 = (&wv[2].x)[tap], w3 = (&wv[3].x)[tap];
            a0 += w0 * v.x; a1 += w1 * v.y; a2 += w2 * v.z; a3 += w3 * v.w;
        }
    }
    float4 o;
    o.x = silu_f(a0); o.y = silu_f(a1); o.z = silu_f(a2); o.w = silu_f(a3);
    *reinterpret_cast<float4*>(&g_xs[l * DI + d]) = o;
}

// ============ K4: dt = softplus(xdbl[:, :12] @ W_dt^T + b_dt), 16 tokens/block ============
__global__ __launch_bounds__(384) void k_dt(const float* __restrict__ Wdt, const float* __restrict__ bdt) {
    __shared__ float sW[DTR * DI];     // [r][d]
    __shared__ float sxd[16][DTR];
    int tid = threadIdx.x;             // 384
    int l0 = blockIdx.x * 16;
    #pragma unroll
    for (int r = 0; r < DTR; r++) sW[r * DI + tid] = Wdt[tid * DTR + r];
    if (tid < 16 * DTR) {
        int tok = tid / DTR, r = tid % DTR;
        sxd[tok][r] = g_xdbl[(l0 + tok) * XDW + r];
    }
    __syncthreads();
    float bb = bdt[tid];
    #pragma unroll 4
    for (int j = 0; j < 16; j++) {
        float acc = bb;
        #pragma unroll
        for (int r = 0; r < DTR; r++) acc += sxd[j][r] * sW[r * DI + tid];
        float e = __expf(-fabsf(acc));
        g_dt[(l0 + j) * DI + tid] = fmaxf(acc, 0.f) + log1pf(e);
    }
}

// ============ K5: A = -exp(A_log) ============
__global__ void k_A(const float* __restrict__ Alog) {
    int i = blockIdx.x * blockDim.x + threadIdx.x;
    if (i < DI * DS) g_A[i] = -expf(Alog[i]);
}

// ============ scan phase 1: per-chunk local state + dt sum ============
__global__ __launch_bounds__(128) void k_scan1() {
    int chunk = blockIdx.y;
    int d = blockIdx.x * 128 + threadIdx.x;
    __shared__ float sB[CLEN][DS];
    for (int i = threadIdx.x; i < CLEN * DS; i += 128) {
        int r = i >> 4, s = i & 15;
        sB[r][s] = g_xdbl[(chunk * CLEN + r) * XDW + DTR + s];
    }
    __syncthreads();
    float Ad[DS], h[DS];
    #pragma unroll
    for (int s = 0; s < DS; s++) { Ad[s] = g_A[d * DS + s]; h[s] = 0.f; }
    float dsum = 0.f;
    for (int i = 0; i < CLEN; i++) {
        int l = chunk * CLEN + i;
        float dtv = g_dt[l * DI + d];
        float xv  = g_xs[l * DI + d];
        float dtx = dtv * xv;
        dsum += dtv;
        #pragma unroll
        for (int s = 0; s < DS; s++)
            h[s] = __expf(dtv * Ad[s]) * h[s] + dtx * sB[i][s];
    }
    int base = (chunk * DI + d) * DS;
    #pragma unroll
    for (int s = 0; s < DS; s++) g_hc[base + s] = h[s];
    g_dts[chunk * DI + d] = dsum;
}

// ============ scan phase 2: inter-chunk prefix ============
__global__ void k_scan2() {
    int idx = blockIdx.x * blockDim.x + threadIdx.x;
    if (idx >= DI * DS) return;
    int d = idx >> 4;
    float a = g_A[idx];
    float h = 0.f;
    for (int c = 0; c < NCH; c++) {
        int off = (c * DI + d) * DS + (idx & 15);
        g_hin[off] = h;
        h = __expf(g_dts[c * DI + d] * a) * h + g_hc[off];
    }
}

// ============ scan phase 3: recompute with carry, emit gated y ============
__global__ __launch_bounds__(128) void k_scan3(const float* __restrict__ Dp) {
    int chunk = blockIdx.y;
    int d = blockIdx.x * 128 + threadIdx.x;
    __shared__ float sB[CLEN][DS];
    __shared__ float sC[CLEN][DS];
    for (int i = threadIdx.x; i < CLEN * DS; i += 128) {
        int r = i >> 4, s = i & 15;
        sB[r][s] = g_xdbl[(chunk * CLEN + r) * XDW + DTR + s];
        sC[r][s] = g_xdbl[(chunk * CLEN + r) * XDW + DTR + DS + s];
    }
    __syncthreads();
    float Ad[DS], h[DS];
    int base = (chunk * DI + d) * DS;
    #pragma unroll
    for (int s = 0; s < DS; s++) { Ad[s] = g_A[d * DS + s]; h[s] = g_hin[base + s]; }
    float Dd = Dp[d];
    for (int i = 0; i < CLEN; i++) {
        int l = chunk * CLEN + i;
        float dtv = g_dt[l * DI + d];
        float xv  = g_xs[l * DI + d];
        float dtx = dtv * xv;
        float yt = 0.f;
        #pragma unroll
        for (int s = 0; s < DS; s++) {
            h[s] = __expf(dtv * Ad[s]) * h[s] + dtx * sB[i][s];
            yt += h[s] * sC[i][s];
        }
        yt += xv * Dd;
        float zv = g_xz[l * (2 * DI) + DI + d];
        g_y[l * DI + d] = yt * silu_f(zv);
    }
}

// ============ K6: fused residual + LN2 + transpose -> ln2T (C, L) ============
// block handles 32 tokens, 256 threads (8 warps x 4 tokens)
__global__ __launch_bounds__(256) void k_ln2t(const float* __restrict__ g2, const float* __restrict__ b2) {
    __shared__ float sm[32 * 193];       // [l_local][c], pad 193
    int l0 = blockIdx.x * 32;
    int w = threadIdx.x >> 5, lane = threadIdx.x & 31;
    #pragma unroll
    for (int j = 0; j < 4; j++) {
        int tok = w * 4 + j;
        int l = l0 + tok;
        float v[6];
        float s = 0.f, q = 0.f;
        #pragma unroll
        for (int k = 0; k < 6; k++) {
            int c = lane + 32 * k;
            v[k] = g_tokens[l * CC + c] + g_om[l * CC + c];
            s += v[k];
            q += v[k] * v[k];
        }
        #pragma unroll
        for (int o = 16; o > 0; o >>= 1) {
            s += __shfl_xor_sync(0xffffffffu, s, o);
            q += __shfl_xor_sync(0xffffffffu, q, o);
        }
        float m = s * (1.f / CC);
        float var = q * (1.f / CC) - m * m;
        float rstd = rsqrtf(var + 1e-5f);
        #pragma unroll
        for (int k = 0; k < 6; k++) {
            int c = lane + 32 * k;
            sm[tok * 193 + c] = (v[k] - m) * rstd * g2[c] + b2[c];
        }
    }
    __syncthreads();
    for (int c = w; c < CC; c += 8)
        g_ln2T[c * LL + l0 + lane] = sm[lane * 193 + c];
}

// ============ K7: pooled -> 16pt rDFT bins 1..7 -> sigmoid weight ============
__global__ __launch_bounds__(256) void k_freq() {
    int c = blockIdx.x;
    int tid = threadIdx.x;
    __shared__ float spart[8][16];
    __shared__ float sp[16];
    __shared__ float smag[8];
    int w = tid >> 5, lane = tid & 31;
    #pragma unroll
    for (int t = 0; t < TT; t++) {
        float v = g_ln2T[c * LL + t * 256 + tid];
        #pragma unroll
        for (int o = 16; o > 0; o >>= 1) v += __shfl_down_sync(0xffffffffu, v, o);
        if (lane == 0) spart[w][t] = v;
    }
    __syncthreads();
    if (tid < 16) {
        float s = 0.f;
        #pragma unroll
        for (int k = 0; k < 8; k++) s += spart[k][tid];
        sp[tid] = s * (1.f / 256.f);
    }
    __syncthreads();
    if (tid >= 1 && tid < 8) {
        float re = 0.f, im = 0.f;
        for (int t = 0; t < TT; t++) {
            float ang = -2.f * 3.14159265358979323846f * (float)(tid * t) / 16.f;
            re += sp[t] * cosf(ang);
            im += sp[t] * sinf(ang);
        }
        smag[tid] = sqrtf(re * re + im * im);
    }
    __syncthreads();
    if (tid == 0) {
        float m = 0.f;
        #pragma unroll
        for (int k = 1; k < 8; k++) m += smag[k];
        m *= (1.f / 7.f);
        g_w[c] = 1.f / (1.f + expf(-m));
    }
}

// ============ K8: bilinear x4 upsample * weight * sigmoid(x) ============
// block = (t = blockIdx.x, c = blockIdx.y), 256 threads, smem tile of 16x16
__global__ __launch_bounds__(256) void k_final(const float* __restrict__ x, float* __restrict__ out) {
    __shared__ float tile[256];
    int t = blockIdx.x, c = blockIdx.y;
    int tid = threadIdx.x;
    float wc = g_w[c];
    tile[tid] = g_ln2T[c * LL + t * 256 + tid] * wc;
    __syncthreads();
    long base = ((long)c * TT + t) * 4096;
    #pragma unroll
    for (int j = 0; j < 16; j++) {
        int pos = j * 256 + tid;
        int h = pos >> 6, w = pos & 63;
        float sh = h * 0.25f - 0.375f;
        float sw = w * 0.25f - 0.375f;
        int ih = (int)floorf(sh); float fh = sh - (float)ih;
        int iw = (int)floorf(sw); float fw = sw - (float)iw;
        int h0 = min(max(ih, 0), 15), h1 = min(max(ih + 1, 0), 15);
        int w0 = min(max(iw, 0), 15), w1 = min(max(iw + 1, 0), 15);
        float p00 = tile[h0 * 16 + w0];
        float p01 = tile[h0 * 16 + w1];
        float p10 = tile[h1 * 16 + w0];
        float p11 = tile[h1 * 16 + w1];
        float v = (1.f - fh) * ((1.f - fw) * p00 + fw * p01)
                +        fh  * ((1.f - fw) * p10 + fw * p11);
        long idx = base + pos;
        out[idx] = v * sigmoid_f(x[idx]);
    }
}

// ---------------- launch ----------------
static float* sym_addr(const void* sym) {
    void* p = nullptr;
    cudaGetSymbolAddress(&p, sym);
    return (float*)p;
}

extern "C" void kernel_launch(void* const* d_in, const int* in_sizes, int n_in,
                              void* d_out, int out_size) {
    const float* x     = (const float*)d_in[0];
    const float* ln1g  = (const float*)d_in[1];
    const float* ln1b  = (const float*)d_in[2];
    const float* ln2g  = (const float*)d_in[3];
    const float* ln2b  = (const float*)d_in[4];
    const float* Win   = (const float*)d_in[5];
    const float* convw = (const float*)d_in[6];
    const float* convb = (const float*)d_in[7];
    const float* Wxp   = (const float*)d_in[8];
    const float* Wdt   = (const float*)d_in[9];
    const float* bdt   = (const float*)d_in[10];
    const float* Alog  = (const float*)d_in[11];
    const float* Dp    = (const float*)d_in[12];
    const float* Wout  = (const float*)d_in[13];
    float* out = (float*)d_out;

    float* p_yln  = sym_addr(g_yln);
    float* p_xz   = sym_addr(g_xz);
    float* p_xs   = sym_addr(g_xs);
    float* p_xdbl = sym_addr(g_xdbl);
    float* p_y    = sym_addr(g_y);
    float* p_om   = sym_addr(g_om);

    // 1. fused pool + LN1
    k_pool_ln1<<<dim3(16, 16), 256>>>(x, ln1g, ln1b);
    // 2. xz = yln @ W_in^T   (4096 x 768, K=192)
    gemm_tn_t<128, 64, 16, 8, 4, false><<<dim3(12, 32), dim3(16, 16)>>>(p_yln, Win, p_xz, LL, 2 * DI, CC);
    // 3. depthwise causal conv + silu -> xs
    k_conv<<<(LL * DI / 4) / 256, 256>>>(convw, convb);
    // 4. x_dbl = xs @ W_xp^T  (4096 x 44, K=384)
    gemm_tn_t<32, 48, 16, 4, 3, true><<<dim3(1, 128), dim3(16, 8)>>>(p_xs, Wxp, p_xdbl, LL, XDW, DI);
    // 5. dt
    k_dt<<<LL / 16, 384>>>(Wdt, bdt);
    // 6. A = -exp(A_log)
    k_A<<<(DI * DS + 255) / 256, 256>>>(Alog);
    // 7-9. chunked selective scan
    k_scan1<<<dim3(3, NCH), 128>>>();
    k_scan2<<<(DI * DS + 255) / 256, 256>>>();
    k_scan3<<<dim3(3, NCH), 128>>>(Dp);
    // 10. out_m = y @ W_out^T (4096 x 192, K=384)
    gemm_tn_t<64, 64, 16, 4, 4, false><<<dim3(3, 64), dim3(16, 16)>>>(p_y, Wout, p_om, LL, CC, DI);
    // 11. LN2(tokens + out_m), transposed output
    k_ln2t<<<LL / 32, 256>>>(ln2g, ln2b);
    // 12. frequency gate
    k_freq<<<CC, 256>>>();
    // 13. upsample * sigmoid(x)
    k_final<<<dim3(TT, CC), 256>>>(x, out);
}